// round 15
// baseline (speedup 1.0000x reference)
#include <cuda_runtime.h>
#include <cuda_fp16.h>
#include <math.h>
#include <stdint.h>

#define BSZ   16384
#define DD    256
#define UU    32
#define NB    8
#define MHD   512
#define RHD   256
#define KCAT  4096   // NB*MHD
#define RNNW  288    // RHD+UU
#define NYD   20
#define NQ    4      // batch quarters for k1->k2 pipelining
#define QROWS (BSZ / NQ)

// ---------------- static device scratch (no allocations allowed) ----------------
__device__ __align__(16) __half g_W1h[(long)NB * MHD * DD]; // [n][h][d] gate-folded W1, fp16
__device__ float g_P[(long)NB * RHD * MHD];                 // [n][r][h] = Bg @ W2
__device__ __align__(16) float g_G[(long)DD * KCAT];        // [d][n*512+h]
__device__ __align__(16) __half g_Gh[(long)DD * KCAT];      // fp16 G
__device__ float g_Pb[NB * RHD];
__device__ float g_F[DD * UU];
__device__ float g_biasz[DD];
__device__ __align__(16) float g_UF[(long)BSZ * DD];
__device__ __align__(16) __half g_Zh[(long)BSZ * DD];       // fp16 zt
__device__ __align__(16) __half g_Xh[(long)BSZ * KCAT];     // fp16 X

// ================= helpers (base-arch only: ldmatrix / mma.sync / cp.async) =================
__device__ __forceinline__ uint32_t smem_u32(const void* p) {
    uint32_t a;
    asm("{ .reg .u64 t; cvta.to.shared.u64 t, %1; cvt.u32.u64 %0, t; }" : "=r"(a) : "l"(p));
    return a;
}
__device__ __forceinline__ void cp16(uint32_t dst, const void* src) {
    asm volatile("cp.async.cg.shared.global [%0], [%1], 16;" :: "r"(dst), "l"(src));
}
#define CP_COMMIT() asm volatile("cp.async.commit_group;")
__device__ __forceinline__ void ldsm4(uint32_t (&r)[4], uint32_t addr) {
    asm volatile("ldmatrix.sync.aligned.m8n8.x4.shared.b16 {%0,%1,%2,%3}, [%4];"
                 : "=r"(r[0]), "=r"(r[1]), "=r"(r[2]), "=r"(r[3]) : "r"(addr));
}
__device__ __forceinline__ void mma16816(float (&d)[4], const uint32_t (&a)[4],
                                         uint32_t b0, uint32_t b1) {
    asm volatile("mma.sync.aligned.m16n8k16.row.col.f32.f16.f16.f32 "
                 "{%0,%1,%2,%3}, {%4,%5,%6,%7}, {%8,%9}, {%0,%1,%2,%3};"
                 : "+f"(d[0]), "+f"(d[1]), "+f"(d[2]), "+f"(d[3])
                 : "r"(a[0]), "r"(a[1]), "r"(a[2]), "r"(a[3]), "r"(b0), "r"(b1));
}
// fast GELU: tanh form with HW tanh.approx (adds ~1e-4 rel rms vs exact erf)
__device__ __forceinline__ float gelu_t(float x) {
    float u = 0.7978845608028654f * fmaf(0.044715f * x, x * x, x);
    float th;
    asm("tanh.approx.f32 %0, %1;" : "=f"(th) : "f"(u));
    return 0.5f * x * (1.f + th);
}

// ---------------- fold gates into W1 ([n][h][d]), fp16, 4 el/thread ----------------
__global__ void kfold(const float* __restrict__ W1, const float* __restrict__ gates) {
    int idx = (blockIdx.x * 256 + threadIdx.x) * 4;   // 2^20 over [n][h][d]
    int n = idx >> 17;
    int d = idx & 255;
    float4 w = *(const float4*)(W1 + idx);
    float4 g = *(const float4*)(gates + n * DD + d);
    __half2 h0 = __floats2half2_rn(w.x / (1.0f + expf(-g.x)), w.y / (1.0f + expf(-g.y)));
    __half2 h1 = __floats2half2_rn(w.z / (1.0f + expf(-g.z)), w.w / (1.0f + expf(-g.w)));
    *(__half2*)(g_W1h + idx) = h0;
    *(__half2*)(g_W1h + idx + 2) = h1;
}

// ---------------- convert zt to fp16, 4 el/thread ----------------
__global__ void kZconv(const float* __restrict__ zt) {
    long i = ((long)blockIdx.x * 256 + threadIdx.x) * 4;   // BSZ*DD = 4M
    float4 v = *(const float4*)(zt + i);
    *(__half2*)(g_Zh + i)     = __floats2half2_rn(v.x, v.y);
    *(__half2*)(g_Zh + i + 2) = __floats2half2_rn(v.z, v.w);
}

// ---------------- convert G to fp16, 4 el/thread ----------------
__global__ void kGconv() {
    long i = ((long)blockIdx.x * 256 + threadIdx.x) * 4;   // DD*KCAT = 2^20
    float4 v = *(const float4*)(g_G + i);
    *(__half2*)(g_Gh + i)     = __floats2half2_rn(v.x, v.y);
    *(__half2*)(g_Gh + i + 2) = __floats2half2_rn(v.z, v.w);
}

// ---------------- batched 64x64 tiled SGEMM (fp32 precompute only) ----------------
__global__ void __launch_bounds__(256) gemm64(
    const float* __restrict__ A, int lda, long sA,
    const float* __restrict__ B, int ldb, long sB,
    float* __restrict__ C, int ldc, long sC, int K)
{
    A += (long)blockIdx.z * sA;
    B += (long)blockIdx.z * sB;
    C += (long)blockIdx.z * sC;
    int bn = blockIdx.x * 64, bm = blockIdx.y * 64;
    __shared__ float As[16][64];
    __shared__ float Bs[16][64];
    int t = threadIdx.x;
    int tr = t >> 4, tc = t & 15;
    float acc[4][4] = {};
    int arow = t >> 2, ak = (t & 3) << 2;
    int bk = t >> 4, boff = (t & 15) << 2;
    for (int k0 = 0; k0 < K; k0 += 16) {
        float4 av = *(const float4*)(A + (long)(bm + arow) * lda + k0 + ak);
        float4 bv = *(const float4*)(B + (long)(k0 + bk) * ldb + bn + boff);
        __syncthreads();
        As[ak + 0][arow] = av.x; As[ak + 1][arow] = av.y;
        As[ak + 2][arow] = av.z; As[ak + 3][arow] = av.w;
        *(float4*)&Bs[bk][boff] = bv;
        __syncthreads();
#pragma unroll
        for (int kk = 0; kk < 16; kk++) {
            float a[4], b[4];
            *(float4*)a = *(float4*)&As[kk][tr << 2];
            *(float4*)b = *(float4*)&Bs[kk][tc << 2];
#pragma unroll
            for (int i = 0; i < 4; i++)
#pragma unroll
                for (int j = 0; j < 4; j++) acc[i][j] = fmaf(a[i], b[j], acc[i][j]);
        }
    }
#pragma unroll
    for (int i = 0; i < 4; i++) {
        float4 o = make_float4(acc[i][0], acc[i][1], acc[i][2], acc[i][3]);
        *(float4*)(C + (long)(bm + (tr << 2) + i) * ldc + bn + (tc << 2)) = o;
    }
}

// ---------------- tiny precompute kernels (warp-per-output) ----------------
__global__ void kPb(const float* __restrict__ rnnB, const float* __restrict__ b2) {
    int g = blockIdx.x * 8 + (threadIdx.x >> 5);      // 2048 outputs
    int lane = threadIdx.x & 31;
    int n = g >> 8, r = g & 255;
    const float* a = rnnB + (long)n * RHD * RNNW + (long)r * RNNW;
    const float* b = b2 + n * RHD;
    float s = 0.f;
#pragma unroll
    for (int i = 0; i < 8; i++) s = fmaf(a[lane + 32 * i], b[lane + 32 * i], s);
#pragma unroll
    for (int off = 16; off; off >>= 1) s += __shfl_xor_sync(0xffffffffu, s, off);
    if (lane == 0) g_Pb[g] = s;
}

__global__ void kbiasz(const float* __restrict__ Wout) {
    int d = blockIdx.x * 8 + (threadIdx.x >> 5);      // 256 outputs
    int lane = threadIdx.x & 31;
    float s = 0.f;
#pragma unroll
    for (int i = 0; i < 64; i++) {
        int idx = lane + 32 * i;                       // 0..2047
        int n = idx >> 8, r = idx & 255;
        s = fmaf(Wout[(long)n * DD * RHD + (long)d * RHD + r], g_Pb[n * RHD + r], s);
    }
#pragma unroll
    for (int off = 16; off; off >>= 1) s += __shfl_xor_sync(0xffffffffu, s, off);
    if (lane == 0) g_biasz[d] = s;
}

__global__ void kF(const float* __restrict__ Wout, const float* __restrict__ rnnB) {
    int g = blockIdx.x * 8 + (threadIdx.x >> 5);      // 8192 outputs
    int lane = threadIdx.x & 31;
    int d = g >> 5, u = g & 31;
    float s = 0.f;
#pragma unroll
    for (int i = 0; i < 64; i++) {
        int idx = lane + 32 * i;
        int n = idx >> 8, r = idx & 255;
        s = fmaf(Wout[(long)n * DD * RHD + (long)d * RHD + r],
                 rnnB[(long)n * RHD * RNNW + (long)r * RNNW + RHD + u], s);
    }
#pragma unroll
    for (int off = 16; off; off >>= 1) s += __shfl_xor_sync(0xffffffffu, s, off);
    if (lane == 0) g_F[d * UU + u] = s;
}

// g_UF[b][d] = biasz[d] + dt * sum_u ut[b][u] * F[d][u]
__global__ void __launch_bounds__(256) kUF(const float* __restrict__ ut, const float* __restrict__ dtp) {
    __shared__ float Fs[UU * DD];
    __shared__ float uts[64 * UU];
    long b0 = (long)blockIdx.x * 64;
    int t = threadIdx.x;
    for (int idx = t; idx < DD * UU; idx += 256) {
        int d = idx >> 5, u = idx & 31;
        Fs[u * DD + d] = g_F[idx];
    }
    for (int idx = t; idx < 64 * UU; idx += 256) uts[idx] = ut[b0 * UU + idx];
    float dtv = dtp[0];
    float bz = g_biasz[t];
    __syncthreads();
    for (int r = 0; r < 64; r++) {
        float s = 0.f;
#pragma unroll
        for (int u = 0; u < UU; u++) s = fmaf(uts[r * UU + u], Fs[u * DD + t], s);
        g_UF[(b0 + r) * DD + t] = fmaf(dtv, s, bz);
    }
}

// ============ K1: Xh = fp16(GELU(LN(zt @ W1f[n]^T + b1))) — R8 form, row-quarter ============
// CTA 64x512, 512 threads (warp grid 2x8, warp tile 32x64), K=256 in 8 chunks of 32.
// smem: A 2buf x 4KB (8KB) + B 2buf x 32KB (64KB) = 73728 B
#define K1_SMEM 73728

__global__ void __launch_bounds__(512) k1_mma(
    const float* __restrict__ b1, const float* __restrict__ lng, const float* __restrict__ lnb,
    long rowBase)
{
    extern __shared__ __align__(128) char sm1[];
    const uint32_t sb = smem_u32(sm1);
    const int t = threadIdx.x;
    const int lane = t & 31, wid = t >> 5;
    const int wy = wid >> 3, wx = wid & 7;
    const int n = blockIdx.x;
    const long b0 = rowBase + (long)blockIdx.y * 64;

    __shared__ float b1s[512], lngs[512], lnbs[512];
    __shared__ float redS[8][64], redQ[8][64];
    __shared__ float muS[64], rsS[64];

    b1s[t]  = b1[n * MHD + t];
    lngs[t] = lng[n * MHD + t];
    lnbs[t] = lnb[n * MHD + t];

    const __half* W1B = g_W1h + ((long)n << 17);

    auto load_chunk = [&](int c, int buf) {
        int kb = c * 32;
        if (t < 256) {   // A: 256 cp.async
            int row = t >> 2, cu = t & 3;
            const __half* src = g_Zh + (b0 + row) * DD + kb + cu * 8;
            uint32_t dst = sb + buf * 4096 + row * 64 + ((cu ^ ((row >> 1) & 3)) << 4);
            cp16(dst, src);
        }
#pragma unroll
        for (int j = 0; j < 4; j++) {   // B: 2048 cp.async
            int id = t + 512 * j;
            int row = id >> 2, cu = id & 3;
            const __half* src = W1B + (long)row * DD + kb + cu * 8;
            uint32_t dst = sb + 8192 + buf * 32768 + row * 64 + ((cu ^ ((row >> 1) & 3)) << 4);
            cp16(dst, src);
        }
    };

    float acc[2][8][4];
#pragma unroll
    for (int a = 0; a < 2; a++)
#pragma unroll
        for (int b = 0; b < 8; b++)
#pragma unroll
            for (int c = 0; c < 4; c++) acc[a][b][c] = 0.f;

    load_chunk(0, 0);
    CP_COMMIT();
    for (int c = 0; c < 8; c++) {
        int buf = c & 1;
        if (c + 1 < 8) {
            load_chunk(c + 1, (c + 1) & 1);
            CP_COMMIT();
            asm volatile("cp.async.wait_group 1;");
        } else {
            asm volatile("cp.async.wait_group 0;");
        }
        __syncthreads();
        uint32_t aB = sb + buf * 4096;
        uint32_t bB = sb + 8192 + buf * 32768;
#pragma unroll
        for (int k16 = 0; k16 < 2; k16++) {
            uint32_t ah[2][4];
#pragma unroll
            for (int rf = 0; rf < 2; rf++) {
                int r = wy * 32 + rf * 16 + (lane & 15);
                int cu = k16 * 2 + (lane >> 4);
                uint32_t off = r * 64 + ((cu ^ ((r >> 1) & 3)) << 4);
                ldsm4(ah[rf], aB + off);
            }
#pragma unroll
            for (int bf = 0; bf < 4; bf++) {
                int rb = wx * 64 + bf * 16 + (lane & 15);
                int cu = k16 * 2 + (lane >> 4);
                uint32_t off = rb * 64 + ((cu ^ ((rb >> 1) & 3)) << 4);
                uint32_t bh[4];
                ldsm4(bh, bB + off);
#pragma unroll
                for (int rf = 0; rf < 2; rf++) {
                    mma16816(acc[rf][2 * bf],     ah[rf], bh[0], bh[2]);
                    mma16816(acc[rf][2 * bf + 1], ah[rf], bh[1], bh[3]);
                }
            }
        }
        __syncthreads();
    }

    // ---- bias + LN stats ----
    float sums[2][2] = {{0.f, 0.f}, {0.f, 0.f}};
    float sqs[2][2]  = {{0.f, 0.f}, {0.f, 0.f}};
#pragma unroll
    for (int rf = 0; rf < 2; rf++)
#pragma unroll
        for (int nf = 0; nf < 8; nf++)
#pragma unroll
            for (int h = 0; h < 2; h++)
#pragma unroll
                for (int p = 0; p < 2; p++) {
                    int col = wx * 64 + nf * 8 + (lane & 3) * 2 + p;
                    float x = acc[rf][nf][h * 2 + p] + b1s[col];
                    acc[rf][nf][h * 2 + p] = x;
                    sums[rf][h] += x;
                    sqs[rf][h]  += x * x;
                }
#pragma unroll
    for (int rf = 0; rf < 2; rf++)
#pragma unroll
        for (int h = 0; h < 2; h++) {
            sums[rf][h] += __shfl_xor_sync(0xffffffffu, sums[rf][h], 1);
            sums[rf][h] += __shfl_xor_sync(0xffffffffu, sums[rf][h], 2);
            sqs[rf][h]  += __shfl_xor_sync(0xffffffffu, sqs[rf][h], 1);
            sqs[rf][h]  += __shfl_xor_sync(0xffffffffu, sqs[rf][h], 2);
        }
    if ((lane & 3) == 0) {
#pragma unroll
        for (int rf = 0; rf < 2; rf++)
#pragma unroll
            for (int h = 0; h < 2; h++) {
                int r = wy * 32 + rf * 16 + h * 8 + (lane >> 2);
                redS[wx][r] = sums[rf][h];
                redQ[wx][r] = sqs[rf][h];
            }
    }
    __syncthreads();
    if (t < 64) {
        float s = 0.f, q = 0.f;
#pragma unroll
        for (int w = 0; w < 8; w++) { s += redS[w][t]; q += redQ[w][t]; }
        float mu = s * (1.f / 512.f);
        float var = q * (1.f / 512.f) - mu * mu;
        muS[t] = mu;
        rsS[t] = rsqrtf(var + 1e-5f);
    }
    __syncthreads();

    // ---- LN scale/shift + GELU(tanh) + fp16 store ----
#pragma unroll
    for (int rf = 0; rf < 2; rf++)
#pragma unroll
        for (int h = 0; h < 2; h++) {
            int r = wy * 32 + rf * 16 + h * 8 + (lane >> 2);
            float mu = muS[r], rs = rsS[r];
            long grow = b0 + r;
            __half* xh = g_Xh + grow * KCAT + (long)n * MHD;
#pragma unroll
            for (int nf = 0; nf < 8; nf++) {
                int col = wx * 64 + nf * 8 + (lane & 3) * 2;
                float x0 = (acc[rf][nf][h * 2 + 0] - mu) * rs * lngs[col]     + lnbs[col];
                float x1 = (acc[rf][nf][h * 2 + 1] - mu) * rs * lngs[col + 1] + lnbs[col + 1];
                x0 = gelu_t(x0);
                x1 = gelu_t(x1);
                *(__half2*)(xh + col) = __floats2half2_rn(x0, x1);
            }
        }
}

// ============ K2: zt1 = Xh @ Gh^T + UF ; fused yt1 — R8 form, row-quarter ============
// CTA 128x256, 512 threads (warp grid 4x4, warp tile 32x64), K=4096 in 128 chunks of 32.
// 3-stage pipeline: A 3x8KB (24KB) + B 3x16KB (48KB) = 73728.
// fused-epilogue smem reuse: zs 64KB + Cs 20KB + Dms 2.5KB -> 90112
#define K2_SMEM 90112

__global__ void __launch_bounds__(512) k2_mma(
    float* __restrict__ out, float* __restrict__ outY,
    const float* __restrict__ ut, const float* __restrict__ dtp,
    const float* __restrict__ C, const float* __restrict__ Dm,
    long mBase)
{
    extern __shared__ __align__(128) char sm2[];
    const uint32_t sb = smem_u32(sm2);
    const int t = threadIdx.x;
    const int lane = t & 31, wid = t >> 5;
    const int wy = wid >> 2, wx = wid & 3;
    const long bm = mBase + (long)blockIdx.x * 128;

    auto load_chunk = [&](int c, int buf) {
        int kb = c * 32;
        {   // A: 512 cp.async, 128 rows x 64B
            int row = t >> 2, cu = t & 3;
            const __half* src = g_Xh + (bm + row) * (long)KCAT + kb + cu * 8;
            uint32_t dst = sb + buf * 8192 + row * 64 + ((cu ^ ((row >> 1) & 3)) << 4);
            cp16(dst, src);
        }
#pragma unroll
        for (int j = 0; j < 2; j++) {   // B: 1024 cp.async, 256 rows x 64B
            int id = t + 512 * j;
            int row = id >> 2, cu = id & 3;
            const __half* src = g_Gh + (long)row * KCAT + kb + cu * 8;
            uint32_t dst = sb + 24576 + buf * 16384 + row * 64 + ((cu ^ ((row >> 1) & 3)) << 4);
            cp16(dst, src);
        }
    };

    float acc[2][8][4];
#pragma unroll
    for (int a = 0; a < 2; a++)
#pragma unroll
        for (int b = 0; b < 8; b++)
#pragma unroll
            for (int c = 0; c < 4; c++) acc[a][b][c] = 0.f;

    load_chunk(0, 0); CP_COMMIT();
    load_chunk(1, 1); CP_COMMIT();
    int buf = 0;
    for (int c = 0; c < 128; c++) {
        if (c < 126) asm volatile("cp.async.wait_group 1;");
        else         asm volatile("cp.async.wait_group 0;");
        __syncthreads();
        if (c + 2 < 128) {
            int nb = buf + 2; if (nb >= 3) nb -= 3;
            load_chunk(c + 2, nb);
            CP_COMMIT();
        }
        uint32_t aB = sb + buf * 8192;
        uint32_t bB = sb + 24576 + buf * 16384;
#pragma unroll
        for (int k16 = 0; k16 < 2; k16++) {
            uint32_t ah[2][4];
#pragma unroll
            for (int rf = 0; rf < 2; rf++) {
                int r = wy * 32 + rf * 16 + (lane & 15);
                int cu = k16 * 2 + (lane >> 4);
                uint32_t off = r * 64 + ((cu ^ ((r >> 1) & 3)) << 4);
                ldsm4(ah[rf], aB + off);
            }
#pragma unroll
            for (int bf = 0; bf < 4; bf++) {
                int rb = wx * 64 + bf * 16 + (lane & 15);
                int cu = k16 * 2 + (lane >> 4);
                uint32_t off = rb * 64 + ((cu ^ ((rb >> 1) & 3)) << 4);
                uint32_t bh[4];
                ldsm4(bh, bB + off);
#pragma unroll
                for (int rf = 0; rf < 2; rf++) {
                    mma16816(acc[rf][2 * bf],     ah[rf], bh[0], bh[2]);
                    mma16816(acc[rf][2 * bf + 1], ah[rf], bh[1], bh[3]);
                }
            }
        }
        if (++buf == 3) buf = 0;
    }

    // ---- epilogue: zt1 = acc + UF -> gmem (fp32) + smem (fp16 for y) ----
    __syncthreads();   // pipeline smem now dead; reuse for zs/Cs/Dms
    __half* zs = (__half*)sm2;                       // [128][256] fp16, 64 KB
    float* Cs  = (float*)(sm2 + 65536);              // [256][20] transposed, 20 KB
    float* Dms = (float*)(sm2 + 65536 + 20480);      // [32][20] transposed, 2.5 KB
#pragma unroll
    for (int rf = 0; rf < 2; rf++)
#pragma unroll
        for (int h = 0; h < 2; h++) {
            int lrow = wy * 32 + rf * 16 + h * 8 + (lane >> 2);
            long row = bm + lrow;
#pragma unroll
            for (int nf = 0; nf < 8; nf++) {
                int col = wx * 64 + nf * 8 + (lane & 3) * 2;
                float2 u = *(const float2*)(g_UF + row * DD + col);
                float o0 = acc[rf][nf][h * 2 + 0] + u.x;
                float o1 = acc[rf][nf][h * 2 + 1] + u.y;
                *(float2*)(out + row * DD + col) = make_float2(o0, o1);
                *(__half2*)(zs + lrow * DD + col) = __floats2half2_rn(o0, o1);
            }
        }
    // stage C (transposed) and Dm (transposed)
    for (int i = t; i < NYD * DD; i += 512) {
        int y = i >> 8, d = i & 255;
        Cs[d * NYD + y] = C[i];
    }
    for (int i = t; i < NYD * UU; i += 512) {
        int y = i >> 5, u = i & 31;
        Dms[u * NYD + y] = Dm[i];
    }
    __syncthreads();

    // ---- y: 128 rows x 20 outputs = 2560, 5 per thread ----
    float dtv = dtp[0];
#pragma unroll
    for (int o = 0; o < 5; o++) {
        int idx = t + o * 512;
        int lrow = idx / NYD, y = idx - lrow * NYD;
        const __half2* zr = (const __half2*)(zs + lrow * DD);
        float s = 0.f;
#pragma unroll
        for (int d2 = 0; d2 < DD / 2; d2++) {
            float2 zv = __half22float2(zr[d2]);
            s = fmaf(zv.x, Cs[(2 * d2) * NYD + y], s);
            s = fmaf(zv.y, Cs[(2 * d2 + 1) * NYD + y], s);
        }
        float sm = 0.f;
        const float* ur = ut + (bm + lrow) * UU;
#pragma unroll
        for (int u = 0; u < UU; u++) sm = fmaf(ur[u], Dms[u * NYD + y], sm);
        outY[(bm + lrow) * NYD + y] = s + dtv * sm;
    }
}

// ---------------- launch ----------------
extern "C" void kernel_launch(void* const* d_in, const int* in_sizes, int n_in,
                              void* d_out, int out_size) {
    (void)in_sizes; (void)n_in; (void)out_size;
    const float* zt    = (const float*)d_in[0];
    const float* dt    = (const float*)d_in[1];
    const float* ut    = (const float*)d_in[2];
    const float* gates = (const float*)d_in[3];
    const float* W1    = (const float*)d_in[4];
    const float* b1    = (const float*)d_in[5];
    const float* ln_g  = (const float*)d_in[6];
    const float* ln_b  = (const float*)d_in[7];
    const float* W2    = (const float*)d_in[8];
    const float* b2    = (const float*)d_in[9];
    // d_in[10] lam_r, d_in[11] lam_i unused (lambda drops out at h0=0)
    const float* rnnB  = (const float*)d_in[12];
    const float* Wout  = (const float*)d_in[13];
    const float* C     = (const float*)d_in[14];
    const float* Dm    = (const float*)d_in[15];
    float* out = (float*)d_out;                    // [B*D] zt1 then [B*20] yt1

    float* gP; cudaGetSymbolAddress((void**)&gP, g_P);
    float* gG; cudaGetSymbolAddress((void**)&gG, g_G);

    cudaFuncSetAttribute(k1_mma, cudaFuncAttributeMaxDynamicSharedMemorySize, K1_SMEM);
    cudaFuncSetAttribute(k2_mma, cudaFuncAttributeMaxDynamicSharedMemorySize, K2_SMEM);

    // lazily-created streams + events (host objects only, created pre-capture)
    static cudaStream_t s2 = nullptr, s3 = nullptr;
    static cudaEvent_t evF = nullptr, evJ = nullptr, evEnd = nullptr;
    static cudaEvent_t evQ[NQ] = {nullptr, nullptr, nullptr, nullptr};
    if (s2 == nullptr) {
        cudaStreamCreateWithFlags(&s2, cudaStreamNonBlocking);
        cudaStreamCreateWithFlags(&s3, cudaStreamNonBlocking);
        cudaEventCreateWithFlags(&evF, cudaEventDisableTiming);
        cudaEventCreateWithFlags(&evJ, cudaEventDisableTiming);
        cudaEventCreateWithFlags(&evEnd, cudaEventDisableTiming);
        for (int q = 0; q < NQ; q++) cudaEventCreateWithFlags(&evQ[q], cudaEventDisableTiming);
    }

    // main stream: k1 deps first
    kfold<<<1024, 256>>>(W1, gates);
    kZconv<<<4096, 256>>>(zt);

    // fork: side stream s2 runs the k2-only precompute chain concurrently with k1
    cudaEventRecord(evF, 0);
    cudaStreamWaitEvent(s2, evF, 0);

    gemm64<<<dim3(8, 4, NB), 256, 0, s2>>>(rnnB, RNNW, (long)RHD * RNNW,
                                           W2, MHD, (long)RHD * MHD,
                                           gP, MHD, (long)RHD * MHD, RHD);
    gemm64<<<dim3(8, 4, NB), 256, 0, s2>>>(Wout, RHD, (long)DD * RHD,
                                           gP, MHD, (long)RHD * MHD,
                                           gG, KCAT, (long)MHD, RHD);
    kGconv<<<1024, 256, 0, s2>>>();
    kPb<<<256, 256, 0, s2>>>(rnnB, b2);
    kbiasz<<<32, 256, 0, s2>>>(Wout);
    kF<<<1024, 256, 0, s2>>>(Wout, rnnB);
    kUF<<<BSZ / 64, 256, 0, s2>>>(ut, dt);
    cudaEventRecord(evJ, s2);

    // s3 needs the side chain (G, UF) before any k2 quarter
    cudaStreamWaitEvent(s3, evJ, 0);

    // pipelined k1 -> k2 over batch quarters
    for (int q = 0; q < NQ; q++) {
        long rowBase = (long)q * QROWS;
        k1_mma<<<dim3(NB, QROWS / 64), 512, K1_SMEM>>>(b1, ln_g, ln_b, rowBase);
        cudaEventRecord(evQ[q], 0);
        cudaStreamWaitEvent(s3, evQ[q], 0);
        k2_mma<<<QROWS / 128, 512, K2_SMEM, s3>>>(out, out + (long)BSZ * DD,
                                                  ut, dt, C, Dm, rowBase);
    }

    // join s3 back to the capture-origin stream
    cudaEventRecord(evEnd, s3);
    cudaStreamWaitEvent(0, evEnd, 0);
}

// round 16
// speedup vs baseline: 2.0525x; 2.0525x over previous
#include <cuda_runtime.h>
#include <cuda_fp16.h>
#include <math.h>
#include <stdint.h>

#define BSZ   16384
#define DD    256
#define UU    32
#define NB    8
#define MHD   512
#define RHD   256
#define KCAT  4096   // NB*MHD
#define RNNW  288    // RHD+UU
#define NYD   20
#define NH    2      // halves for k1->k2 concurrent pipelining
#define HROWS (BSZ / NH)

// ---------------- static device scratch (no allocations allowed) ----------------
__device__ __align__(16) __half g_W1h[(long)NB * MHD * DD]; // [n][h][d] gate-folded W1, fp16
__device__ float g_P[(long)NB * RHD * MHD];                 // [n][r][h] = Bg @ W2
__device__ __align__(16) float g_G[(long)DD * KCAT];        // [d][n*512+h]
__device__ __align__(16) __half g_Gh[(long)DD * KCAT];      // fp16 G
__device__ float g_Pb[NB * RHD];
__device__ float g_F[DD * UU];
__device__ float g_biasz[DD];
__device__ __align__(16) float g_UF[(long)BSZ * DD];
__device__ __align__(16) __half g_Zh[(long)BSZ * DD];       // fp16 zt
__device__ __align__(16) __half g_Xh[(long)BSZ * KCAT];     // fp16 X

// ================= helpers (base-arch only: ldmatrix / mma.sync / cp.async) =================
__device__ __forceinline__ uint32_t smem_u32(const void* p) {
    uint32_t a;
    asm("{ .reg .u64 t; cvta.to.shared.u64 t, %1; cvt.u32.u64 %0, t; }" : "=r"(a) : "l"(p));
    return a;
}
__device__ __forceinline__ void cp16(uint32_t dst, const void* src) {
    asm volatile("cp.async.cg.shared.global [%0], [%1], 16;" :: "r"(dst), "l"(src));
}
#define CP_COMMIT() asm volatile("cp.async.commit_group;")
__device__ __forceinline__ void ldsm4(uint32_t (&r)[4], uint32_t addr) {
    asm volatile("ldmatrix.sync.aligned.m8n8.x4.shared.b16 {%0,%1,%2,%3}, [%4];"
                 : "=r"(r[0]), "=r"(r[1]), "=r"(r[2]), "=r"(r[3]) : "r"(addr));
}
__device__ __forceinline__ void mma16816(float (&d)[4], const uint32_t (&a)[4],
                                         uint32_t b0, uint32_t b1) {
    asm volatile("mma.sync.aligned.m16n8k16.row.col.f32.f16.f16.f32 "
                 "{%0,%1,%2,%3}, {%4,%5,%6,%7}, {%8,%9}, {%0,%1,%2,%3};"
                 : "+f"(d[0]), "+f"(d[1]), "+f"(d[2]), "+f"(d[3])
                 : "r"(a[0]), "r"(a[1]), "r"(a[2]), "r"(a[3]), "r"(b0), "r"(b1));
}
// fast GELU: tanh form with HW tanh.approx (adds ~1e-4 rel rms vs exact erf)
__device__ __forceinline__ float gelu_t(float x) {
    float u = 0.7978845608028654f * fmaf(0.044715f * x, x * x, x);
    float th;
    asm("tanh.approx.f32 %0, %1;" : "=f"(th) : "f"(u));
    return 0.5f * x * (1.f + th);
}

// ---------------- fold gates into W1 ([n][h][d]), fp16, 4 el/thread ----------------
__global__ void kfold(const float* __restrict__ W1, const float* __restrict__ gates) {
    int idx = (blockIdx.x * 256 + threadIdx.x) * 4;   // 2^20 over [n][h][d]
    int n = idx >> 17;
    int d = idx & 255;
    float4 w = *(const float4*)(W1 + idx);
    float4 g = *(const float4*)(gates + n * DD + d);
    __half2 h0 = __floats2half2_rn(w.x / (1.0f + expf(-g.x)), w.y / (1.0f + expf(-g.y)));
    __half2 h1 = __floats2half2_rn(w.z / (1.0f + expf(-g.z)), w.w / (1.0f + expf(-g.w)));
    *(__half2*)(g_W1h + idx) = h0;
    *(__half2*)(g_W1h + idx + 2) = h1;
}

// ---------------- convert zt to fp16, 4 el/thread ----------------
__global__ void kZconv(const float* __restrict__ zt) {
    long i = ((long)blockIdx.x * 256 + threadIdx.x) * 4;   // BSZ*DD = 4M
    float4 v = *(const float4*)(zt + i);
    *(__half2*)(g_Zh + i)     = __floats2half2_rn(v.x, v.y);
    *(__half2*)(g_Zh + i + 2) = __floats2half2_rn(v.z, v.w);
}

// ---------------- convert G to fp16, 4 el/thread ----------------
__global__ void kGconv() {
    long i = ((long)blockIdx.x * 256 + threadIdx.x) * 4;   // DD*KCAT = 2^20
    float4 v = *(const float4*)(g_G + i);
    *(__half2*)(g_Gh + i)     = __floats2half2_rn(v.x, v.y);
    *(__half2*)(g_Gh + i + 2) = __floats2half2_rn(v.z, v.w);
}

// ---------------- batched 64x64 tiled SGEMM (fp32 precompute only) ----------------
__global__ void __launch_bounds__(256) gemm64(
    const float* __restrict__ A, int lda, long sA,
    const float* __restrict__ B, int ldb, long sB,
    float* __restrict__ C, int ldc, long sC, int K)
{
    A += (long)blockIdx.z * sA;
    B += (long)blockIdx.z * sB;
    C += (long)blockIdx.z * sC;
    int bn = blockIdx.x * 64, bm = blockIdx.y * 64;
    __shared__ float As[16][64];
    __shared__ float Bs[16][64];
    int t = threadIdx.x;
    int tr = t >> 4, tc = t & 15;
    float acc[4][4] = {};
    int arow = t >> 2, ak = (t & 3) << 2;
    int bk = t >> 4, boff = (t & 15) << 2;
    for (int k0 = 0; k0 < K; k0 += 16) {
        float4 av = *(const float4*)(A + (long)(bm + arow) * lda + k0 + ak);
        float4 bv = *(const float4*)(B + (long)(k0 + bk) * ldb + bn + boff);
        __syncthreads();
        As[ak + 0][arow] = av.x; As[ak + 1][arow] = av.y;
        As[ak + 2][arow] = av.z; As[ak + 3][arow] = av.w;
        *(float4*)&Bs[bk][boff] = bv;
        __syncthreads();
#pragma unroll
        for (int kk = 0; kk < 16; kk++) {
            float a[4], b[4];
            *(float4*)a = *(float4*)&As[kk][tr << 2];
            *(float4*)b = *(float4*)&Bs[kk][tc << 2];
#pragma unroll
            for (int i = 0; i < 4; i++)
#pragma unroll
                for (int j = 0; j < 4; j++) acc[i][j] = fmaf(a[i], b[j], acc[i][j]);
        }
    }
#pragma unroll
    for (int i = 0; i < 4; i++) {
        float4 o = make_float4(acc[i][0], acc[i][1], acc[i][2], acc[i][3]);
        *(float4*)(C + (long)(bm + (tr << 2) + i) * ldc + bn + (tc << 2)) = o;
    }
}

// ---------------- tiny precompute kernels (warp-per-output) ----------------
__global__ void kPb(const float* __restrict__ rnnB, const float* __restrict__ b2) {
    int g = blockIdx.x * 8 + (threadIdx.x >> 5);      // 2048 outputs
    int lane = threadIdx.x & 31;
    int n = g >> 8, r = g & 255;
    const float* a = rnnB + (long)n * RHD * RNNW + (long)r * RNNW;
    const float* b = b2 + n * RHD;
    float s = 0.f;
#pragma unroll
    for (int i = 0; i < 8; i++) s = fmaf(a[lane + 32 * i], b[lane + 32 * i], s);
#pragma unroll
    for (int off = 16; off; off >>= 1) s += __shfl_xor_sync(0xffffffffu, s, off);
    if (lane == 0) g_Pb[g] = s;
}

__global__ void kbiasz(const float* __restrict__ Wout) {
    int d = blockIdx.x * 8 + (threadIdx.x >> 5);      // 256 outputs
    int lane = threadIdx.x & 31;
    float s = 0.f;
#pragma unroll
    for (int i = 0; i < 64; i++) {
        int idx = lane + 32 * i;                       // 0..2047
        int n = idx >> 8, r = idx & 255;
        s = fmaf(Wout[(long)n * DD * RHD + (long)d * RHD + r], g_Pb[n * RHD + r], s);
    }
#pragma unroll
    for (int off = 16; off; off >>= 1) s += __shfl_xor_sync(0xffffffffu, s, off);
    if (lane == 0) g_biasz[d] = s;
}

__global__ void kF(const float* __restrict__ Wout, const float* __restrict__ rnnB) {
    int g = blockIdx.x * 8 + (threadIdx.x >> 5);      // 8192 outputs
    int lane = threadIdx.x & 31;
    int d = g >> 5, u = g & 31;
    float s = 0.f;
#pragma unroll
    for (int i = 0; i < 64; i++) {
        int idx = lane + 32 * i;
        int n = idx >> 8, r = idx & 255;
        s = fmaf(Wout[(long)n * DD * RHD + (long)d * RHD + r],
                 rnnB[(long)n * RHD * RNNW + (long)r * RNNW + RHD + u], s);
    }
#pragma unroll
    for (int off = 16; off; off >>= 1) s += __shfl_xor_sync(0xffffffffu, s, off);
    if (lane == 0) g_F[d * UU + u] = s;
}

// g_UF[b][d] = biasz[d] + dt * sum_u ut[b][u] * F[d][u]
__global__ void __launch_bounds__(256) kUF(const float* __restrict__ ut, const float* __restrict__ dtp) {
    __shared__ float Fs[UU * DD];
    __shared__ float uts[64 * UU];
    long b0 = (long)blockIdx.x * 64;
    int t = threadIdx.x;
    for (int idx = t; idx < DD * UU; idx += 256) {
        int d = idx >> 5, u = idx & 31;
        Fs[u * DD + d] = g_F[idx];
    }
    for (int idx = t; idx < 64 * UU; idx += 256) uts[idx] = ut[b0 * UU + idx];
    float dtv = dtp[0];
    float bz = g_biasz[t];
    __syncthreads();
    for (int r = 0; r < 64; r++) {
        float s = 0.f;
#pragma unroll
        for (int u = 0; u < UU; u++) s = fmaf(uts[r * UU + u], Fs[u * DD + t], s);
        g_UF[(b0 + r) * DD + t] = fmaf(dtv, s, bz);
    }
}

// ============ K1: Xh = fp16(GELU(LN(zt @ W1f[n]^T + b1))) — R8 form, row-range ============
// CTA 64x512, 512 threads (warp grid 2x8, warp tile 32x64), K=256 in 8 chunks of 32.
// smem: A 2buf x 4KB (8KB) + B 2buf x 32KB (64KB) = 73728 B
#define K1_SMEM 73728

__global__ void __launch_bounds__(512) k1_mma(
    const float* __restrict__ b1, const float* __restrict__ lng, const float* __restrict__ lnb,
    long rowBase)
{
    extern __shared__ __align__(128) char sm1[];
    const uint32_t sb = smem_u32(sm1);
    const int t = threadIdx.x;
    const int lane = t & 31, wid = t >> 5;
    const int wy = wid >> 3, wx = wid & 7;
    const int n = blockIdx.x;
    const long b0 = rowBase + (long)blockIdx.y * 64;

    __shared__ float b1s[512], lngs[512], lnbs[512];
    __shared__ float redS[8][64], redQ[8][64];
    __shared__ float muS[64], rsS[64];

    b1s[t]  = b1[n * MHD + t];
    lngs[t] = lng[n * MHD + t];
    lnbs[t] = lnb[n * MHD + t];

    const __half* W1B = g_W1h + ((long)n << 17);

    auto load_chunk = [&](int c, int buf) {
        int kb = c * 32;
        if (t < 256) {   // A: 256 cp.async
            int row = t >> 2, cu = t & 3;
            const __half* src = g_Zh + (b0 + row) * DD + kb + cu * 8;
            uint32_t dst = sb + buf * 4096 + row * 64 + ((cu ^ ((row >> 1) & 3)) << 4);
            cp16(dst, src);
        }
#pragma unroll
        for (int j = 0; j < 4; j++) {   // B: 2048 cp.async
            int id = t + 512 * j;
            int row = id >> 2, cu = id & 3;
            const __half* src = W1B + (long)row * DD + kb + cu * 8;
            uint32_t dst = sb + 8192 + buf * 32768 + row * 64 + ((cu ^ ((row >> 1) & 3)) << 4);
            cp16(dst, src);
        }
    };

    float acc[2][8][4];
#pragma unroll
    for (int a = 0; a < 2; a++)
#pragma unroll
        for (int b = 0; b < 8; b++)
#pragma unroll
            for (int c = 0; c < 4; c++) acc[a][b][c] = 0.f;

    load_chunk(0, 0);
    CP_COMMIT();
    for (int c = 0; c < 8; c++) {
        int buf = c & 1;
        if (c + 1 < 8) {
            load_chunk(c + 1, (c + 1) & 1);
            CP_COMMIT();
            asm volatile("cp.async.wait_group 1;");
        } else {
            asm volatile("cp.async.wait_group 0;");
        }
        __syncthreads();
        uint32_t aB = sb + buf * 4096;
        uint32_t bB = sb + 8192 + buf * 32768;
#pragma unroll
        for (int k16 = 0; k16 < 2; k16++) {
            uint32_t ah[2][4];
#pragma unroll
            for (int rf = 0; rf < 2; rf++) {
                int r = wy * 32 + rf * 16 + (lane & 15);
                int cu = k16 * 2 + (lane >> 4);
                uint32_t off = r * 64 + ((cu ^ ((r >> 1) & 3)) << 4);
                ldsm4(ah[rf], aB + off);
            }
#pragma unroll
            for (int bf = 0; bf < 4; bf++) {
                int rb = wx * 64 + bf * 16 + (lane & 15);
                int cu = k16 * 2 + (lane >> 4);
                uint32_t off = rb * 64 + ((cu ^ ((rb >> 1) & 3)) << 4);
                uint32_t bh[4];
                ldsm4(bh, bB + off);
#pragma unroll
                for (int rf = 0; rf < 2; rf++) {
                    mma16816(acc[rf][2 * bf],     ah[rf], bh[0], bh[2]);
                    mma16816(acc[rf][2 * bf + 1], ah[rf], bh[1], bh[3]);
                }
            }
        }
        __syncthreads();
    }

    // ---- bias + LN stats ----
    float sums[2][2] = {{0.f, 0.f}, {0.f, 0.f}};
    float sqs[2][2]  = {{0.f, 0.f}, {0.f, 0.f}};
#pragma unroll
    for (int rf = 0; rf < 2; rf++)
#pragma unroll
        for (int nf = 0; nf < 8; nf++)
#pragma unroll
            for (int h = 0; h < 2; h++)
#pragma unroll
                for (int p = 0; p < 2; p++) {
                    int col = wx * 64 + nf * 8 + (lane & 3) * 2 + p;
                    float x = acc[rf][nf][h * 2 + p] + b1s[col];
                    acc[rf][nf][h * 2 + p] = x;
                    sums[rf][h] += x;
                    sqs[rf][h]  += x * x;
                }
#pragma unroll
    for (int rf = 0; rf < 2; rf++)
#pragma unroll
        for (int h = 0; h < 2; h++) {
            sums[rf][h] += __shfl_xor_sync(0xffffffffu, sums[rf][h], 1);
            sums[rf][h] += __shfl_xor_sync(0xffffffffu, sums[rf][h], 2);
            sqs[rf][h]  += __shfl_xor_sync(0xffffffffu, sqs[rf][h], 1);
            sqs[rf][h]  += __shfl_xor_sync(0xffffffffu, sqs[rf][h], 2);
        }
    if ((lane & 3) == 0) {
#pragma unroll
        for (int rf = 0; rf < 2; rf++)
#pragma unroll
            for (int h = 0; h < 2; h++) {
                int r = wy * 32 + rf * 16 + h * 8 + (lane >> 2);
                redS[wx][r] = sums[rf][h];
                redQ[wx][r] = sqs[rf][h];
            }
    }
    __syncthreads();
    if (t < 64) {
        float s = 0.f, q = 0.f;
#pragma unroll
        for (int w = 0; w < 8; w++) { s += redS[w][t]; q += redQ[w][t]; }
        float mu = s * (1.f / 512.f);
        float var = q * (1.f / 512.f) - mu * mu;
        muS[t] = mu;
        rsS[t] = rsqrtf(var + 1e-5f);
    }
    __syncthreads();

    // ---- LN scale/shift + GELU(tanh) + fp16 store ----
#pragma unroll
    for (int rf = 0; rf < 2; rf++)
#pragma unroll
        for (int h = 0; h < 2; h++) {
            int r = wy * 32 + rf * 16 + h * 8 + (lane >> 2);
            float mu = muS[r], rs = rsS[r];
            long grow = b0 + r;
            __half* xh = g_Xh + grow * KCAT + (long)n * MHD;
#pragma unroll
            for (int nf = 0; nf < 8; nf++) {
                int col = wx * 64 + nf * 8 + (lane & 3) * 2;
                float x0 = (acc[rf][nf][h * 2 + 0] - mu) * rs * lngs[col]     + lnbs[col];
                float x1 = (acc[rf][nf][h * 2 + 1] - mu) * rs * lngs[col + 1] + lnbs[col + 1];
                x0 = gelu_t(x0);
                x1 = gelu_t(x1);
                *(__half2*)(xh + col) = __floats2half2_rn(x0, x1);
            }
        }
}

// ============ K2: zt1 = Xh @ Gh^T + UF ; fused yt1 — R8 form, row-range ============
// CTA 128x256, 512 threads (warp grid 4x4, warp tile 32x64), K=4096 in 128 chunks of 32.
// 3-stage pipeline: A 3x8KB (24KB) + B 3x16KB (48KB) = 73728.
// fused-epilogue smem reuse: zs 64KB + Cs 20KB + Dms 2.5KB -> 90112
#define K2_SMEM 90112

__global__ void __launch_bounds__(512) k2_mma(
    float* __restrict__ out, float* __restrict__ outY,
    const float* __restrict__ ut, const float* __restrict__ dtp,
    const float* __restrict__ C, const float* __restrict__ Dm,
    long mBase)
{
    extern __shared__ __align__(128) char sm2[];
    const uint32_t sb = smem_u32(sm2);
    const int t = threadIdx.x;
    const int lane = t & 31, wid = t >> 5;
    const int wy = wid >> 2, wx = wid & 3;
    const long bm = mBase + (long)blockIdx.x * 128;

    auto load_chunk = [&](int c, int buf) {
        int kb = c * 32;
        {   // A: 512 cp.async, 128 rows x 64B
            int row = t >> 2, cu = t & 3;
            const __half* src = g_Xh + (bm + row) * (long)KCAT + kb + cu * 8;
            uint32_t dst = sb + buf * 8192 + row * 64 + ((cu ^ ((row >> 1) & 3)) << 4);
            cp16(dst, src);
        }
#pragma unroll
        for (int j = 0; j < 2; j++) {   // B: 1024 cp.async, 256 rows x 64B
            int id = t + 512 * j;
            int row = id >> 2, cu = id & 3;
            const __half* src = g_Gh + (long)row * KCAT + kb + cu * 8;
            uint32_t dst = sb + 24576 + buf * 16384 + row * 64 + ((cu ^ ((row >> 1) & 3)) << 4);
            cp16(dst, src);
        }
    };

    float acc[2][8][4];
#pragma unroll
    for (int a = 0; a < 2; a++)
#pragma unroll
        for (int b = 0; b < 8; b++)
#pragma unroll
            for (int c = 0; c < 4; c++) acc[a][b][c] = 0.f;

    load_chunk(0, 0); CP_COMMIT();
    load_chunk(1, 1); CP_COMMIT();
    int buf = 0;
    for (int c = 0; c < 128; c++) {
        if (c < 126) asm volatile("cp.async.wait_group 1;");
        else         asm volatile("cp.async.wait_group 0;");
        __syncthreads();
        if (c + 2 < 128) {
            int nb = buf + 2; if (nb >= 3) nb -= 3;
            load_chunk(c + 2, nb);
            CP_COMMIT();
        }
        uint32_t aB = sb + buf * 8192;
        uint32_t bB = sb + 24576 + buf * 16384;
#pragma unroll
        for (int k16 = 0; k16 < 2; k16++) {
            uint32_t ah[2][4];
#pragma unroll
            for (int rf = 0; rf < 2; rf++) {
                int r = wy * 32 + rf * 16 + (lane & 15);
                int cu = k16 * 2 + (lane >> 4);
                uint32_t off = r * 64 + ((cu ^ ((r >> 1) & 3)) << 4);
                ldsm4(ah[rf], aB + off);
            }
#pragma unroll
            for (int bf = 0; bf < 4; bf++) {
                int rb = wx * 64 + bf * 16 + (lane & 15);
                int cu = k16 * 2 + (lane >> 4);
                uint32_t off = rb * 64 + ((cu ^ ((rb >> 1) & 3)) << 4);
                uint32_t bh[4];
                ldsm4(bh, bB + off);
#pragma unroll
                for (int rf = 0; rf < 2; rf++) {
                    mma16816(acc[rf][2 * bf],     ah[rf], bh[0], bh[2]);
                    mma16816(acc[rf][2 * bf + 1], ah[rf], bh[1], bh[3]);
                }
            }
        }
        if (++buf == 3) buf = 0;
    }

    // ---- epilogue: zt1 = acc + UF -> gmem (fp32) + smem (fp16 for y) ----
    __syncthreads();   // pipeline smem now dead; reuse for zs/Cs/Dms
    __half* zs = (__half*)sm2;                       // [128][256] fp16, 64 KB
    float* Cs  = (float*)(sm2 + 65536);              // [256][20] transposed, 20 KB
    float* Dms = (float*)(sm2 + 65536 + 20480);      // [32][20] transposed, 2.5 KB
#pragma unroll
    for (int rf = 0; rf < 2; rf++)
#pragma unroll
        for (int h = 0; h < 2; h++) {
            int lrow = wy * 32 + rf * 16 + h * 8 + (lane >> 2);
            long row = bm + lrow;
#pragma unroll
            for (int nf = 0; nf < 8; nf++) {
                int col = wx * 64 + nf * 8 + (lane & 3) * 2;
                float2 u = *(const float2*)(g_UF + row * DD + col);
                float o0 = acc[rf][nf][h * 2 + 0] + u.x;
                float o1 = acc[rf][nf][h * 2 + 1] + u.y;
                *(float2*)(out + row * DD + col) = make_float2(o0, o1);
                *(__half2*)(zs + lrow * DD + col) = __floats2half2_rn(o0, o1);
            }
        }
    // stage C (transposed) and Dm (transposed)
    for (int i = t; i < NYD * DD; i += 512) {
        int y = i >> 8, d = i & 255;
        Cs[d * NYD + y] = C[i];
    }
    for (int i = t; i < NYD * UU; i += 512) {
        int y = i >> 5, u = i & 31;
        Dms[u * NYD + y] = Dm[i];
    }
    __syncthreads();

    // ---- y: 128 rows x 20 outputs = 2560, 5 per thread ----
    float dtv = dtp[0];
#pragma unroll
    for (int o = 0; o < 5; o++) {
        int idx = t + o * 512;
        int lrow = idx / NYD, y = idx - lrow * NYD;
        const __half2* zr = (const __half2*)(zs + lrow * DD);
        float s = 0.f;
#pragma unroll
        for (int d2 = 0; d2 < DD / 2; d2++) {
            float2 zv = __half22float2(zr[d2]);
            s = fmaf(zv.x, Cs[(2 * d2) * NYD + y], s);
            s = fmaf(zv.y, Cs[(2 * d2 + 1) * NYD + y], s);
        }
        float sm = 0.f;
        const float* ur = ut + (bm + lrow) * UU;
#pragma unroll
        for (int u = 0; u < UU; u++) sm = fmaf(ur[u], Dms[u * NYD + y], sm);
        outY[(bm + lrow) * NYD + y] = s + dtv * sm;
    }
}

// ---------------- launch ----------------
extern "C" void kernel_launch(void* const* d_in, const int* in_sizes, int n_in,
                              void* d_out, int out_size) {
    (void)in_sizes; (void)n_in; (void)out_size;
    const float* zt    = (const float*)d_in[0];
    const float* dt    = (const float*)d_in[1];
    const float* ut    = (const float*)d_in[2];
    const float* gates = (const float*)d_in[3];
    const float* W1    = (const float*)d_in[4];
    const float* b1    = (const float*)d_in[5];
    const float* ln_g  = (const float*)d_in[6];
    const float* ln_b  = (const float*)d_in[7];
    const float* W2    = (const float*)d_in[8];
    const float* b2    = (const float*)d_in[9];
    // d_in[10] lam_r, d_in[11] lam_i unused (lambda drops out at h0=0)
    const float* rnnB  = (const float*)d_in[12];
    const float* Wout  = (const float*)d_in[13];
    const float* C     = (const float*)d_in[14];
    const float* Dm    = (const float*)d_in[15];
    float* out = (float*)d_out;                    // [B*D] zt1 then [B*20] yt1

    float* gP; cudaGetSymbolAddress((void**)&gP, g_P);
    float* gG; cudaGetSymbolAddress((void**)&gG, g_G);

    cudaFuncSetAttribute(k1_mma, cudaFuncAttributeMaxDynamicSharedMemorySize, K1_SMEM);
    cudaFuncSetAttribute(k2_mma, cudaFuncAttributeMaxDynamicSharedMemorySize, K2_SMEM);

    // lazily-created streams + events (host objects only, created pre-capture)
    static cudaStream_t s2 = nullptr, sH[NH] = {nullptr, nullptr};
    static cudaEvent_t evF = nullptr, evJ = nullptr;
    static cudaEvent_t evK1[NH] = {nullptr, nullptr};
    static cudaEvent_t evK2[NH] = {nullptr, nullptr};
    if (s2 == nullptr) {
        cudaStreamCreateWithFlags(&s2, cudaStreamNonBlocking);
        cudaEventCreateWithFlags(&evF, cudaEventDisableTiming);
        cudaEventCreateWithFlags(&evJ, cudaEventDisableTiming);
        for (int q = 0; q < NH; q++) {
            cudaStreamCreateWithFlags(&sH[q], cudaStreamNonBlocking);
            cudaEventCreateWithFlags(&evK1[q], cudaEventDisableTiming);
            cudaEventCreateWithFlags(&evK2[q], cudaEventDisableTiming);
        }
    }

    // main stream: k1 deps first
    kfold<<<1024, 256>>>(W1, gates);
    kZconv<<<4096, 256>>>(zt);

    // fork: side stream s2 runs the k2-only precompute chain concurrently with k1
    cudaEventRecord(evF, 0);
    cudaStreamWaitEvent(s2, evF, 0);

    gemm64<<<dim3(8, 4, NB), 256, 0, s2>>>(rnnB, RNNW, (long)RHD * RNNW,
                                           W2, MHD, (long)RHD * MHD,
                                           gP, MHD, (long)RHD * MHD, RHD);
    gemm64<<<dim3(8, 4, NB), 256, 0, s2>>>(Wout, RHD, (long)DD * RHD,
                                           gP, MHD, (long)RHD * MHD,
                                           gG, KCAT, (long)MHD, RHD);
    kGconv<<<1024, 256, 0, s2>>>();
    kPb<<<256, 256, 0, s2>>>(rnnB, b2);
    kbiasz<<<32, 256, 0, s2>>>(Wout);
    kF<<<1024, 256, 0, s2>>>(Wout, rnnB);
    kUF<<<BSZ / 64, 256, 0, s2>>>(ut, dt);
    cudaEventRecord(evJ, s2);

    // k1 halves on the main stream; each k2 half on its OWN stream so the
    // halves run CONCURRENTLY (k2 is per-CTA latency bound — serial halves
    // double its time, R15's failure mode)
    for (int q = 0; q < NH; q++) {
        long rowBase = (long)q * HROWS;
        k1_mma<<<dim3(NB, HROWS / 64), 512, K1_SMEM>>>(b1, ln_g, ln_b, rowBase);
        cudaEventRecord(evK1[q], 0);
        cudaStreamWaitEvent(sH[q], evK1[q], 0);
        cudaStreamWaitEvent(sH[q], evJ, 0);
        k2_mma<<<HROWS / 128, 512, K2_SMEM, sH[q]>>>(out, out + (long)BSZ * DD,
                                                     ut, dt, C, Dm, rowBase);
        cudaEventRecord(evK2[q], sH[q]);
    }

    // join all k2 halves back to the capture-origin stream
    for (int q = 0; q < NH; q++) cudaStreamWaitEvent(0, evK2[q], 0);
}